// round 7
// baseline (speedup 1.0000x reference)
#include <cuda_runtime.h>
#include <cstdint>

// ---------------------------------------------------------------------------
// WaveBNN R6/R7: split-row conv kernel (2 threads/row, per-half cp.async
// streams, named barriers) -> global bit scratch -> split-j FC kernel.
// (R7 = R6 resubmit after infra failure; design re-verified.)
// ---------------------------------------------------------------------------

#define OUTCH 16
#define NWORDS 45
#define NWPAD 48
#define FC1N 64
#define FC2N 5
#define ROWS_PB 64          // rows per conv block
#define CTPB 128            // conv threads per block (2 per row)
#define FTPB 256            // fc threads per block
#define XST 27              // staging stride (odd -> conflict-free; max cols 26)
#define MAXROWS 65536

// device scratch (no allocation allowed)
__device__ uint32_t           d_wbits[FC1N * NWPAD];
__device__ unsigned long long d_convWp[4 * 8 * 3];   // packed (W[2p],W[2p+1])*A
__device__ unsigned long long d_convBp[4 * 8];       // packed folded bias pairs
__device__ float              d_A1[FC1N], d_B1[FC1N];
__device__ uint32_t           d_abits[NWORDS * MAXROWS];   // 11.8 MB bit scratch

// ---------------- PTX helpers ----------------
__device__ __forceinline__ unsigned long long pk2(float lo, float hi) {
    unsigned long long d;
    asm("mov.b64 %0, {%1, %2};" : "=l"(d) : "f"(lo), "f"(hi));
    return d;
}
__device__ __forceinline__ void unpk2(unsigned long long v, float& lo, float& hi) {
    asm("mov.b64 {%0, %1}, %2;" : "=f"(lo), "=f"(hi) : "l"(v));
}
__device__ __forceinline__ unsigned long long ffma2(
    unsigned long long a, unsigned long long b, unsigned long long c) {
    unsigned long long d;
    asm("fma.rn.f32x2 %0, %1, %2, %3;" : "=l"(d) : "l"(a), "l"(b), "l"(c));
    return d;
}
__device__ __forceinline__ void cp_async4(uint32_t saddr, const float* gaddr) {
    asm volatile("cp.async.ca.shared.global [%0], [%1], 4;" :: "r"(saddr), "l"(gaddr));
}
#define CP_COMMIT() asm volatile("cp.async.commit_group;")
#define CP_WAIT1()  asm volatile("cp.async.wait_group 1;")
#define CP_WAIT0()  asm volatile("cp.async.wait_group 0;")
#define HBAR(id)    asm volatile("bar.sync %0, 64;" :: "r"(id) : "memory")

// ---------------------------------------------------------------------------
// prep: blocks 0..11 pack fc1 weight bits, block 12 folds BN constants
// ---------------------------------------------------------------------------
__global__ void prep_all(
    const float* w0, const float* g0, const float* b0, const float* m0, const float* v0,
    const float* w1, const float* g1b, const float* b1b, const float* m1b, const float* v1b,
    const float* w2, const float* g2, const float* b2, const float* m2, const float* v2,
    const float* w3, const float* g3, const float* b3, const float* m3, const float* v3,
    const float* g1, const float* b1, const float* m1, const float* v1,
    const float* fc1w)
{
    int tid = threadIdx.x;
    if (blockIdx.x == 12) {
        if (tid < 64) {
            int br = tid >> 4, c = tid & 15;
            int p = c >> 1, h = c & 1;
            const float* ws[4] = {w0, w1, w2, w3};
            const float* gs[4] = {g0, g1b, g2, g3};
            const float* bs[4] = {b0, b1b, b2, b3};
            const float* ms[4] = {m0, m1b, m2, m3};
            const float* vs[4] = {v0, v1b, v2, v3};
            double A = (double)gs[br][c] * rsqrt((double)vs[br][c] + 1e-5);
            float Af = (float)A;
            float* bp = (float*)d_convBp;
            bp[(br * 8 + p) * 2 + h] = (float)((double)bs[br][c] - (double)ms[br][c] * A);
            float* wp = (float*)d_convWp;
            #pragma unroll
            for (int k = 0; k < 3; k++) {
                float wv = ws[br][c * 3 + k];
                float s = (wv > 0.f) ? 1.f : ((wv < 0.f) ? -1.f : 0.f);
                wp[(((br * 8 + p) * 3) + k) * 2 + h] = s * Af;
            }
        } else if (tid < 128) {
            int j = tid - 64;
            double A = (double)g1[j] * rsqrt((double)v1[j] + 1e-5);
            d_A1[j] = (float)A;
            d_B1[j] = (float)((double)b1[j] - (double)m1[j] * A);
        }
        return;
    }
    int gid = blockIdx.x * 256 + tid;
    if (gid >= FC1N * NWPAD) return;
    int j = gid / NWPAD, wi = gid % NWPAD;
    const int OFF[4] = {0, 176, 352, 704};
    const int LPa[4] = {11, 11, 22, 46};
    uint32_t wrd = 0;
    #pragma unroll 4
    for (int i = 0; i < 32; i++) {
        int gb = wi * 32 + i;
        if (gb < 1440) {
            int grp = gb >> 4, c = gb & 15, br, t;
            if (grp < 11)      { br = 0; t = grp; }
            else if (grp < 22) { br = 1; t = grp - 11; }
            else if (grp < 44) { br = 2; t = grp - 22; }
            else               { br = 3; t = grp - 44; }
            int col = OFF[br] + c * LPa[br] + t;
            if (fc1w[j * 1440 + col] > 0.f) wrd |= (1u << i);
        }
    }
    d_wbits[gid] = wrd;
}

// ---------------------------------------------------------------------------
// conv kernel helpers
// ---------------------------------------------------------------------------
// stage ROWS_PB x COLS slab (pitch L) into sdst (stride XST) using 64 threads
template<int COLS, int L>
__device__ __forceinline__ void stage64(
    float* __restrict__ sdst, const float* __restrict__ xg,
    int rowbase, int c0, int ht)
{
    uint32_t sb = (uint32_t)__cvta_generic_to_shared(sdst);
    const float* gp = xg + (size_t)rowbase * L + c0;
    #pragma unroll
    for (int i = ht; i < ROWS_PB * COLS; i += 64) {
        int r = i / COLS, c = i - r * COLS;
        cp_async4(sb + (uint32_t)(r * XST + c) * 4, gp + (size_t)r * L + c);
    }
}

__device__ __forceinline__ void load_branch_g(
    int br, unsigned long long (&Wp)[8][3], unsigned long long (&Bp)[8])
{
    #pragma unroll
    for (int p = 0; p < 8; p++) {
        Wp[p][0] = d_convWp[(br * 8 + p) * 3 + 0];
        Wp[p][1] = d_convWp[(br * 8 + p) * 3 + 1];
        Wp[p][2] = d_convWp[(br * 8 + p) * 3 + 2];
        Bp[p]    = d_convBp[br * 8 + p];
    }
}

// conv NP pooled groups; on odd group completes a 32-bit word -> STG scratch
template<int NP>
__device__ __forceinline__ void run_chunk(
    const float* __restrict__ sx,
    const unsigned long long (&Wp)[8][3], const unsigned long long (&Bp)[8],
    int gbase, int row, int rows, uint32_t& acc)
{
    float xa = sx[0], xb = sx[1];
    unsigned long long dA = pk2(xa, xa), dB = pk2(xb, xb);
    #pragma unroll 2
    for (int t = 0; t < NP; t++) {
        float xc = sx[2 * t + 2];
        float xd = sx[2 * t + 3];
        unsigned long long dC = pk2(xc, xc), dD = pk2(xd, xd);
        uint32_t mask = 0;
        #pragma unroll
        for (int p = 0; p < 8; p++) {
            unsigned long long y0 = ffma2(dA, Wp[p][0],
                                    ffma2(dB, Wp[p][1],
                                    ffma2(dC, Wp[p][2], Bp[p])));
            unsigned long long y1 = ffma2(dB, Wp[p][0],
                                    ffma2(dC, Wp[p][1],
                                    ffma2(dD, Wp[p][2], Bp[p])));
            float a0, b0, a1, b1;
            unpk2(y0, a0, b0);
            unpk2(y1, a1, b1);
            if (fmaxf(a0, a1) > 0.f) mask |= (1u << (2 * p));
            if (fmaxf(b0, b1) > 0.f) mask |= (1u << (2 * p + 1));
        }
        int g = gbase + t;
        if (g & 1) d_abits[(size_t)(g >> 1) * rows + row] = acc | (mask << 16);
        else       acc = mask;
        dA = dC; dB = dD;
    }
}

// ---------------------------------------------------------------------------
// conv kernel: 64 rows/block, 2 threads/row (role A = branches 0-2, words 0-21;
// role B = branch 3 (D1), words 22-44). Per-role double-buffered cp.async.
// ---------------------------------------------------------------------------
__global__ void __launch_bounds__(CTPB)
conv_kernel(const float* __restrict__ xA,  const float* __restrict__ xD3,
            const float* __restrict__ xD2, const float* __restrict__ xD1,
            int rows)
{
    __shared__ float s_buf[4][ROWS_PB * XST];   // A0,A1,B0,B1 : 27.6 KB

    int tid = threadIdx.x;
    int ht  = tid & 63;          // thread-in-half
    int roleB = tid >> 6;
    int rowbase = blockIdx.x * ROWS_PB;
    int row = rowbase + ht;

    const float* sx0;
    const float* sx1;
    uint32_t acc = 0;
    unsigned long long Wp[8][3], Bp[8];

    if (!roleB) {
        float* b0 = s_buf[0];
        float* b1 = s_buf[1];
        sx0 = &b0[ht * XST];
        sx1 = &b1[ht * XST];
        // chunks: (xA,0,11,g0) (xD3,0,11,g11) (xD2,0,11,g22) (xD2,22,11,g33)
        stage64<24, 24>(b0, xA,  rowbase, 0, ht); CP_COMMIT();
        stage64<24, 24>(b1, xD3, rowbase, 0, ht); CP_COMMIT();

        CP_WAIT1(); HBAR(1);
        load_branch_g(0, Wp, Bp);
        run_chunk<11>(sx0, Wp, Bp, 0, row, rows, acc);
        HBAR(1);
        stage64<24, 47>(b0, xD2, rowbase, 0, ht); CP_COMMIT();

        CP_WAIT1(); HBAR(1);
        load_branch_g(1, Wp, Bp);
        run_chunk<11>(sx1, Wp, Bp, 11, row, rows, acc);
        HBAR(1);
        stage64<24, 47>(b1, xD2, rowbase, 22, ht); CP_COMMIT();

        CP_WAIT1(); HBAR(1);
        load_branch_g(2, Wp, Bp);
        run_chunk<11>(sx0, Wp, Bp, 22, row, rows, acc);

        CP_WAIT0(); HBAR(1);
        run_chunk<11>(sx1, Wp, Bp, 33, row, rows, acc);
        // groups 0..43 -> words 0..21 all written (43 odd)
    } else {
        float* b0 = s_buf[2];
        float* b1 = s_buf[3];
        sx0 = &b0[ht * XST];
        sx1 = &b1[ht * XST];
        // chunks: (xD1,0,12,g44) (xD1,24,12,g56) (xD1,48,11,g68) (xD1,70,11,g79)
        stage64<26, 94>(b0, xD1, rowbase, 0,  ht); CP_COMMIT();
        stage64<26, 94>(b1, xD1, rowbase, 24, ht); CP_COMMIT();
        load_branch_g(3, Wp, Bp);

        CP_WAIT1(); HBAR(2);
        run_chunk<12>(sx0, Wp, Bp, 44, row, rows, acc);
        HBAR(2);
        stage64<24, 94>(b0, xD1, rowbase, 48, ht); CP_COMMIT();

        CP_WAIT1(); HBAR(2);
        run_chunk<12>(sx1, Wp, Bp, 56, row, rows, acc);
        HBAR(2);
        stage64<24, 94>(b1, xD1, rowbase, 70, ht); CP_COMMIT();

        CP_WAIT1(); HBAR(2);
        run_chunk<11>(sx0, Wp, Bp, 68, row, rows, acc);

        CP_WAIT0(); HBAR(2);
        run_chunk<11>(sx1, Wp, Bp, 79, row, rows, acc);
        // groups 44..89 -> words 22..44 all written (89 odd)
    }
}

// ---------------------------------------------------------------------------
// FC kernel: 2 threads per row, each handles 32 of 64 FC1 outputs; combine
// FC2 partials via shfl_xor. No barriers, no big smem.
// ---------------------------------------------------------------------------
__global__ void __launch_bounds__(FTPB)
fc_kernel(const float* __restrict__ fc2w, const float* __restrict__ fc2b,
          float* __restrict__ out, int rows)
{
    int gid = blockIdx.x * FTPB + threadIdx.x;
    int row = gid >> 1;
    int jh  = gid & 1;
    if (row >= rows) return;

    // load activation bits (coalesced: lane pairs share addresses)
    uint32_t a[NWPAD];
    #pragma unroll
    for (int w = 0; w < NWORDS; w++) a[w] = d_abits[(size_t)w * rows + row];
    a[45] = 0; a[46] = 0; a[47] = 0;

    float o0, o1, o2, o3, o4;
    if (jh == 0) { o0 = fc2b[0]; o1 = fc2b[1]; o2 = fc2b[2]; o3 = fc2b[3]; o4 = fc2b[4]; }
    else         { o0 = 0.f; o1 = 0.f; o2 = 0.f; o3 = 0.f; o4 = 0.f; }

    int j0 = jh * 32;
    #pragma unroll 4
    for (int jj = 0; jj < 32; jj++) {
        int j = j0 + jj;
        const uint4* wj = reinterpret_cast<const uint4*>(&d_wbits[j * NWPAD]);
        int s = 0;
        #pragma unroll
        for (int q = 0; q < NWPAD / 4; q++) {
            uint4 wv = __ldg(&wj[q]);
            s += __popc(a[4 * q + 0] ^ wv.x) + __popc(a[4 * q + 1] ^ wv.y)
               + __popc(a[4 * q + 2] ^ wv.z) + __popc(a[4 * q + 3] ^ wv.w);
        }
        float d = (float)(1440 - 2 * s);               // exact integer dot
        float val = fmaf(d, __ldg(&d_A1[j]), __ldg(&d_B1[j]));
        float sg = (val > 0.0f) ? 1.0f : -1.0f;
        o0 = fmaf(sg, __ldg(&fc2w[0 * FC1N + j]), o0);
        o1 = fmaf(sg, __ldg(&fc2w[1 * FC1N + j]), o1);
        o2 = fmaf(sg, __ldg(&fc2w[2 * FC1N + j]), o2);
        o3 = fmaf(sg, __ldg(&fc2w[3 * FC1N + j]), o3);
        o4 = fmaf(sg, __ldg(&fc2w[4 * FC1N + j]), o4);
    }

    // combine the two j-halves (lanes l, l^1 share a row)
    o0 += __shfl_xor_sync(0xffffffffu, o0, 1);
    o1 += __shfl_xor_sync(0xffffffffu, o1, 1);
    o2 += __shfl_xor_sync(0xffffffffu, o2, 1);
    o3 += __shfl_xor_sync(0xffffffffu, o3, 1);
    o4 += __shfl_xor_sync(0xffffffffu, o4, 1);

    if (jh == 0) {
        float* op = out + (size_t)row * FC2N;
        op[0] = o0; op[1] = o1; op[2] = o2; op[3] = o3; op[4] = o4;
    }
}

// ---------------------------------------------------------------------------
// launch: detect input ordering from sizes (interleaved dict order vs grouped)
// ---------------------------------------------------------------------------
extern "C" void kernel_launch(void* const* d_in, const int* in_sizes, int n_in,
                              void* d_out, int out_size)
{
    const float *xA, *xD3, *xD2, *xD1;
    const float *wA,*gA,*bA,*mA,*vA, *wB,*gB,*bB,*mB,*vB;
    const float *wC,*gC,*bC,*mC,*vC, *wD,*gD,*bD,*mD,*vD;
    const float *fc1w,*g1,*b1,*m1,*v1,*fc2w,*fc2b;

    bool interleaved = (in_sizes[1] != in_sizes[0]);

    if (interleaved) {
        xA  = (const float*)d_in[0];
        wA  = (const float*)d_in[1];  gA = (const float*)d_in[2];
        bA  = (const float*)d_in[3];  mA = (const float*)d_in[4];  vA = (const float*)d_in[5];
        xD3 = (const float*)d_in[6];
        wB  = (const float*)d_in[7];  gB = (const float*)d_in[8];
        bB  = (const float*)d_in[9];  mB = (const float*)d_in[10]; vB = (const float*)d_in[11];
        xD2 = (const float*)d_in[12];
        wC  = (const float*)d_in[13]; gC = (const float*)d_in[14];
        bC  = (const float*)d_in[15]; mC = (const float*)d_in[16]; vC = (const float*)d_in[17];
        xD1 = (const float*)d_in[18];
        wD  = (const float*)d_in[19]; gD = (const float*)d_in[20];
        bD  = (const float*)d_in[21]; mD = (const float*)d_in[22]; vD = (const float*)d_in[23];
        fc1w = (const float*)d_in[24];
        g1 = (const float*)d_in[25]; b1 = (const float*)d_in[26];
        m1 = (const float*)d_in[27]; v1 = (const float*)d_in[28];
        fc2w = (const float*)d_in[29]; fc2b = (const float*)d_in[30];
    } else {
        xA  = (const float*)d_in[0];
        xD3 = (const float*)d_in[1];
        xD2 = (const float*)d_in[2];
        xD1 = (const float*)d_in[3];
        wA  = (const float*)d_in[4];  gA = (const float*)d_in[5];
        bA  = (const float*)d_in[6];  mA = (const float*)d_in[7];  vA = (const float*)d_in[8];
        wB  = (const float*)d_in[9];  gB = (const float*)d_in[10];
        bB  = (const float*)d_in[11]; mB = (const float*)d_in[12]; vB = (const float*)d_in[13];
        wC  = (const float*)d_in[14]; gC = (const float*)d_in[15];
        bC  = (const float*)d_in[16]; mC = (const float*)d_in[17]; vC = (const float*)d_in[18];
        wD  = (const float*)d_in[19]; gD = (const float*)d_in[20];
        bD  = (const float*)d_in[21]; mD = (const float*)d_in[22]; vD = (const float*)d_in[23];
        fc1w = (const float*)d_in[24];
        g1 = (const float*)d_in[25]; b1 = (const float*)d_in[26];
        m1 = (const float*)d_in[27]; v1 = (const float*)d_in[28];
        fc2w = (const float*)d_in[29]; fc2b = (const float*)d_in[30];
    }

    int rows = in_sizes[0] / 24;

    prep_all<<<13, 256>>>(wA, gA, bA, mA, vA,
                          wB, gB, bB, mB, vB,
                          wC, gC, bC, mC, vC,
                          wD, gD, bD, mD, vD,
                          g1, b1, m1, v1, fc1w);
    conv_kernel<<<(rows + ROWS_PB - 1) / ROWS_PB, CTPB>>>(xA, xD3, xD2, xD1, rows);
    fc_kernel<<<(2 * rows + FTPB - 1) / FTPB, FTPB>>>(fc2w, fc2b, (float*)d_out, rows);
}